// round 1
// baseline (speedup 1.0000x reference)
#include <cuda_runtime.h>
#include <math.h>

#define D_MODEL 1024
#define N_HEAD  16
#define SEQ     2048
#define BATCH   2
#define HD      64
#define BM      64
#define BN      64
#define SSTRIDE 68   // 64 + 4 pad, multiple of 4 floats for float4 alignment

// Flash-attention forward, fp32, causal, Q=K=V=x.
// CTA: 256 threads as 16x16; each thread owns a 4x4 register tile.
// Smem: Qt (d-major, pre-scaled), KP (K d-major, aliased as P row-major), Vs (row-major).
__global__ __launch_bounds__(256, 2)
void fa_fwd_kernel(const float* __restrict__ x, float* __restrict__ out) {
    extern __shared__ float smem[];
    float* Qt = smem;                   // Qt[k*SSTRIDE + r]
    float* KP = smem + 64 * SSTRIDE;    // Kt[k*SSTRIDE + c]  then  Ps[r*SSTRIDE + c]
    float* Vs = smem + 2 * 64 * SSTRIDE;// Vs[c*SSTRIDE + d]

    const int t  = threadIdx.x;
    const int tx = t & 15;
    const int ty = t >> 4;
    const int r0 = ty << 2;
    const int c0 = tx << 2;

    const int bh = blockIdx.y;          // 0..31
    const int b  = bh >> 4;
    const int h  = bh & 15;
    // reversed so heaviest (most KV tiles) q-tiles launch first
    const int qtile = (int)gridDim.x - 1 - (int)blockIdx.x;
    const int i0 = qtile * BM;

    const float scale = 0.125f * 1.44269504088896340736f; // 1/sqrt(64) * log2(e)

    const float* xb = x + ((size_t)b * SEQ) * D_MODEL + h * HD;

    // ---- Load Q tile, transposed to d-major, pre-scaled ----
    #pragma unroll
    for (int q = 0; q < 4; q++) {
        int idx = t + q * 256;
        int n   = idx >> 4;          // row within tile (query)
        int kq  = (idx & 15) << 2;   // d offset
        float4 v = *(const float4*)(xb + (size_t)(i0 + n) * D_MODEL + kq);
        Qt[(kq + 0) * SSTRIDE + n] = v.x * scale;
        Qt[(kq + 1) * SSTRIDE + n] = v.y * scale;
        Qt[(kq + 2) * SSTRIDE + n] = v.z * scale;
        Qt[(kq + 3) * SSTRIDE + n] = v.w * scale;
    }

    float O[4][4] = {};
    float m[4], l[4];
    #pragma unroll
    for (int i = 0; i < 4; i++) { m[i] = -INFINITY; l[i] = 0.0f; }

    for (int j0 = 0; j0 <= i0; j0 += BN) {
        __syncthreads();  // previous iteration done reading KP/Vs

        // ---- Load K (=V=x) tile: d-major into KP, row-major into Vs ----
        #pragma unroll
        for (int q = 0; q < 4; q++) {
            int idx = t + q * 256;
            int n   = idx >> 4;
            int kq  = (idx & 15) << 2;
            float4 kv = *(const float4*)(xb + (size_t)(j0 + n) * D_MODEL + kq);
            KP[(kq + 0) * SSTRIDE + n] = kv.x;
            KP[(kq + 1) * SSTRIDE + n] = kv.y;
            KP[(kq + 2) * SSTRIDE + n] = kv.z;
            KP[(kq + 3) * SSTRIDE + n] = kv.w;
            *(float4*)(Vs + n * SSTRIDE + kq) = kv;
        }
        __syncthreads();

        // ---- GEMM1: S[r][c] = sum_k Qt[k][r] * Kt[k][c] (already *scale*log2e) ----
        float S[4][4] = {};
        #pragma unroll
        for (int k = 0; k < 64; k++) {
            float4 a  = *(const float4*)(Qt + k * SSTRIDE + r0);
            float4 bb = *(const float4*)(KP + k * SSTRIDE + c0);
            float av[4] = {a.x, a.y, a.z, a.w};
            float bv[4] = {bb.x, bb.y, bb.z, bb.w};
            #pragma unroll
            for (int i = 0; i < 4; i++)
                #pragma unroll
                for (int j = 0; j < 4; j++)
                    S[i][j] += av[i] * bv[j];
        }

        // ---- Causal mask (only the diagonal tile needs it) ----
        if (j0 == i0) {
            #pragma unroll
            for (int i = 0; i < 4; i++)
                #pragma unroll
                for (int j = 0; j < 4; j++)
                    if (c0 + j > r0 + i) S[i][j] = -INFINITY;
        }

        // ---- Online softmax (base-2) ----
        #pragma unroll
        for (int i = 0; i < 4; i++) {
            float mloc = fmaxf(fmaxf(S[i][0], S[i][1]), fmaxf(S[i][2], S[i][3]));
            #pragma unroll
            for (int off = 8; off >= 1; off >>= 1)
                mloc = fmaxf(mloc, __shfl_xor_sync(0xffffffffu, mloc, off));
            float mn = fmaxf(m[i], mloc);
            float alpha = exp2f(m[i] - mn);
            m[i] = mn;
            float rs = 0.0f;
            #pragma unroll
            for (int j = 0; j < 4; j++) {
                S[i][j] = exp2f(S[i][j] - mn);
                rs += S[i][j];
            }
            #pragma unroll
            for (int off = 8; off >= 1; off >>= 1)
                rs += __shfl_xor_sync(0xffffffffu, rs, off);
            l[i] = l[i] * alpha + rs;
            #pragma unroll
            for (int d = 0; d < 4; d++) O[i][d] *= alpha;
        }

        __syncthreads();  // everyone done reading Kt before overwriting with P

        // ---- Store P into KP (row-major) ----
        #pragma unroll
        for (int i = 0; i < 4; i++) {
            float4 p = make_float4(S[i][0], S[i][1], S[i][2], S[i][3]);
            *(float4*)(KP + (r0 + i) * SSTRIDE + c0) = p;
        }
        __syncthreads();

        // ---- GEMM2: O[r][d] += sum_c Ps[r][c] * Vs[c][d] ----
        #pragma unroll
        for (int c = 0; c < 64; c += 4) {
            float4 p[4];
            #pragma unroll
            for (int i = 0; i < 4; i++)
                p[i] = *(const float4*)(KP + (r0 + i) * SSTRIDE + c);
            #pragma unroll
            for (int cc = 0; cc < 4; cc++) {
                float4 v = *(const float4*)(Vs + (c + cc) * SSTRIDE + c0);
                #pragma unroll
                for (int i = 0; i < 4; i++) {
                    float pv = (cc == 0) ? p[i].x : (cc == 1) ? p[i].y
                             : (cc == 2) ? p[i].z : p[i].w;
                    O[i][0] += pv * v.x;
                    O[i][1] += pv * v.y;
                    O[i][2] += pv * v.z;
                    O[i][3] += pv * v.w;
                }
            }
        }
    }

    // ---- Epilogue: normalize and write out ----
    float* ob = out + ((size_t)b * SEQ) * D_MODEL + h * HD;
    #pragma unroll
    for (int i = 0; i < 4; i++) {
        float inv = 1.0f / l[i];
        float4 o = make_float4(O[i][0] * inv, O[i][1] * inv,
                               O[i][2] * inv, O[i][3] * inv);
        *(float4*)(ob + (size_t)(i0 + r0 + i) * D_MODEL + c0) = o;
    }
}

extern "C" void kernel_launch(void* const* d_in, const int* in_sizes, int n_in,
                              void* d_out, int out_size) {
    const float* x = (const float*)d_in[0];
    float* out = (float*)d_out;
    const int smem_bytes = 3 * 64 * SSTRIDE * sizeof(float);  // 52224
    cudaFuncSetAttribute(fa_fwd_kernel,
                         cudaFuncAttributeMaxDynamicSharedMemorySize, smem_bytes);
    dim3 grid(SEQ / BM, BATCH * N_HEAD);
    fa_fwd_kernel<<<grid, 256, smem_bytes>>>(x, out);
}

// round 4
// speedup vs baseline: 3.0508x; 3.0508x over previous
#include <cuda_runtime.h>
#include <math.h>
#include <stdint.h>

#define D_MODEL 1024
#define N_HEAD  16
#define SEQ     2048
#define BATCH   2
#define HD      64
#define BM      64
#define BN      64
#define KVS     68   // KV row stride (floats): conflict-free GEMM1 B-frag reads
#define PS      68   // P row stride: conflict-free GEMM2 A-frag reads

__device__ __forceinline__ uint32_t f2tf(float f) {
    uint32_t u;
    asm("cvt.rna.tf32.f32 %0, %1;" : "=r"(u) : "f"(f));
    return u;
}
__device__ __forceinline__ float fast_exp2(float x) {
    float y;
    asm("ex2.approx.ftz.f32 %0, %1;" : "=f"(y) : "f"(x));
    return y;
}
__device__ __forceinline__ void mma_tf32(float d[4], const uint32_t a[4], const uint32_t b[2]) {
    asm volatile(
        "mma.sync.aligned.m16n8k8.row.col.f32.tf32.tf32.f32 "
        "{%0,%1,%2,%3}, {%4,%5,%6,%7}, {%8,%9}, {%0,%1,%2,%3};"
        : "+f"(d[0]), "+f"(d[1]), "+f"(d[2]), "+f"(d[3])
        : "r"(a[0]), "r"(a[1]), "r"(a[2]), "r"(a[3]), "r"(b[0]), "r"(b[1]));
}

// Flash attention fwd, tf32 tensor-core path, causal, Q=K=V=x.
// 4 warps/CTA; warp w owns q-rows [w*16, w*16+16). 64x64 KV tiles.
__global__ __launch_bounds__(128, 3)
void fa_tf32_kernel(const float* __restrict__ x, float* __restrict__ out) {
    extern __shared__ float smem[];
    float* KV = smem;                       // [kv 0..63][d], stride KVS (tf32 bits)
    float* Vt = smem + 64 * KVS;            // swizzled: phys = d*64 + (kv ^ 4*(d&7))
    float* Pb = smem + 64 * KVS + 64 * 64;  // per-warp [16][PS]

    const int t    = threadIdx.x;
    const int lane = t & 31;
    const int w    = t >> 5;
    const int g    = lane >> 2;   // group id (row within fragment)
    const int q    = lane & 3;    // thread-in-group (col within fragment)

    const int bh = blockIdx.y;
    const int b  = bh >> 4;
    const int h  = bh & 15;
    const int qtile = (int)gridDim.x - 1 - (int)blockIdx.x;  // heavy tiles first
    const int i0 = qtile * BM;
    const int m0 = w * 16;

    const float scale = 0.125f * 1.44269504088896340736f;  // 1/sqrt(64)*log2(e)
    const float* xb = x + ((size_t)b * SEQ) * D_MODEL + h * HD;
    float* Pm = Pb + w * 16 * PS;

    // ---- Load Q fragments (registers, pre-scaled, tf32) ----
    uint32_t QA[8][4];
    {
        const float* q0 = xb + (size_t)(i0 + m0 + g) * D_MODEL;
        const float* q1 = xb + (size_t)(i0 + m0 + g + 8) * D_MODEL;
        #pragma unroll
        for (int ks = 0; ks < 8; ks++) {
            int k0 = ks * 8;
            QA[ks][0] = f2tf(q0[k0 + q] * scale);
            QA[ks][1] = f2tf(q1[k0 + q] * scale);
            QA[ks][2] = f2tf(q0[k0 + q + 4] * scale);
            QA[ks][3] = f2tf(q1[k0 + q + 4] * scale);
        }
    }

    float O[8][4];
    #pragma unroll
    for (int nb = 0; nb < 8; nb++)
        #pragma unroll
        for (int j = 0; j < 4; j++) O[nb][j] = 0.0f;
    float mrow[2] = {-INFINITY, -INFINITY};
    float lrow[2] = {0.0f, 0.0f};

    for (int j0 = 0; j0 <= i0; j0 += BN) {
        __syncthreads();  // prior GEMM1/GEMM2 reads of KV/Vt done

        // ---- Load x tile -> KV (row-major, tf32 converted) ----
        #pragma unroll
        for (int it = 0; it < 8; it++) {
            int idx = t + it * 128;           // 64 rows x 16 float4
            int n   = idx >> 4;
            int kq  = (idx & 15) << 2;
            float4 v = *(const float4*)(xb + (size_t)(j0 + n) * D_MODEL + kq);
            uint4 u;
            u.x = f2tf(v.x); u.y = f2tf(v.y); u.z = f2tf(v.z); u.w = f2tf(v.w);
            *(uint4*)(KV + n * KVS + kq) = u;
        }
        __syncthreads();

        // ---- Fill Vt (swizzled transpose) from KV ----
        #pragma unroll
        for (int dd = 0; dd < 2; dd++)
            #pragma unroll
            for (int kb = 0; kb < 16; kb++) {
                int d  = w * 16 + dd * 8 + g;
                int kv = kb * 4 + q;
                Vt[d * 64 + (kv ^ (4 * (d & 7)))] = KV[kv * KVS + d];
            }

        // ---- GEMM1: S = Qs @ K^T  (B col-major == KV row-major) ----
        float S[8][4];
        #pragma unroll
        for (int nb = 0; nb < 8; nb++)
            #pragma unroll
            for (int j = 0; j < 4; j++) S[nb][j] = 0.0f;

        #pragma unroll
        for (int ks = 0; ks < 8; ks++) {
            int k0 = ks * 8;
            #pragma unroll
            for (int nb = 0; nb < 8; nb++) {
                const uint32_t* bp = (const uint32_t*)(KV + (nb * 8 + g) * KVS + k0 + q);
                uint32_t bfr[2] = { bp[0], bp[4] };
                mma_tf32(S[nb], QA[ks], bfr);
            }
        }

        // ---- Causal mask (diagonal tile only) ----
        if (j0 == i0) {
            #pragma unroll
            for (int nb = 0; nb < 8; nb++) {
                int c = nb * 8 + 2 * q;
                int r0 = m0 + g, r1 = m0 + g + 8;
                if (c     > r0) S[nb][0] = -INFINITY;
                if (c + 1 > r0) S[nb][1] = -INFINITY;
                if (c     > r1) S[nb][2] = -INFINITY;
                if (c + 1 > r1) S[nb][3] = -INFINITY;
            }
        }

        // ---- Online softmax (base-2), rows g and g+8 ----
        #pragma unroll
        for (int r = 0; r < 2; r++) {
            float mx = -INFINITY;
            #pragma unroll
            for (int nb = 0; nb < 8; nb++)
                mx = fmaxf(mx, fmaxf(S[nb][2 * r], S[nb][2 * r + 1]));
            mx = fmaxf(mx, __shfl_xor_sync(0xffffffffu, mx, 1));
            mx = fmaxf(mx, __shfl_xor_sync(0xffffffffu, mx, 2));
            float mn = fmaxf(mrow[r], mx);
            float alpha = fast_exp2(mrow[r] - mn);
            mrow[r] = mn;
            float rs = 0.0f;
            #pragma unroll
            for (int nb = 0; nb < 8; nb++) {
                S[nb][2 * r]     = fast_exp2(S[nb][2 * r] - mn);
                S[nb][2 * r + 1] = fast_exp2(S[nb][2 * r + 1] - mn);
                rs += S[nb][2 * r] + S[nb][2 * r + 1];
            }
            rs += __shfl_xor_sync(0xffffffffu, rs, 1);
            rs += __shfl_xor_sync(0xffffffffu, rs, 2);
            lrow[r] = lrow[r] * alpha + rs;
            #pragma unroll
            for (int nb = 0; nb < 8; nb++) {
                O[nb][2 * r]     *= alpha;
                O[nb][2 * r + 1] *= alpha;
            }
        }

        __syncthreads();  // Vt fill (all warps) visible before GEMM2 reads

        // ---- Store P fragments (tf32) to warp-private smem ----
        #pragma unroll
        for (int nb = 0; nb < 8; nb++) {
            uint2 p0, p1;
            p0.x = f2tf(S[nb][0]); p0.y = f2tf(S[nb][1]);
            p1.x = f2tf(S[nb][2]); p1.y = f2tf(S[nb][3]);
            *(uint2*)(Pm + g * PS + nb * 8 + 2 * q)       = p0;
            *(uint2*)(Pm + (g + 8) * PS + nb * 8 + 2 * q) = p1;
        }
        __syncwarp();

        // ---- GEMM2: O += P @ V  (B col-major == Vt swizzled) ----
        #pragma unroll
        for (int ks = 0; ks < 8; ks++) {
            int k0 = ks * 8;
            uint32_t pa[4];
            pa[0] = *(const uint32_t*)(Pm + g * PS + k0 + q);
            pa[1] = *(const uint32_t*)(Pm + (g + 8) * PS + k0 + q);
            pa[2] = *(const uint32_t*)(Pm + g * PS + k0 + q + 4);
            pa[3] = *(const uint32_t*)(Pm + (g + 8) * PS + k0 + q + 4);
            #pragma unroll
            for (int nb = 0; nb < 8; nb++) {
                int n = nb * 8 + g;
                uint32_t bfr[2];
                bfr[0] = *(const uint32_t*)(Vt + n * 64 + ((k0 + q)     ^ (4 * g)));
                bfr[1] = *(const uint32_t*)(Vt + n * 64 + ((k0 + q + 4) ^ (4 * g)));
                mma_tf32(O[nb], pa, bfr);
            }
        }
        __syncwarp();  // GEMM2 reads of Pm done before next-iter P store
    }

    // ---- Epilogue ----
    float inv0 = 1.0f / lrow[0];
    float inv1 = 1.0f / lrow[1];
    float* o0 = out + ((size_t)b * SEQ + i0 + m0 + g) * D_MODEL + h * HD;
    float* o1 = out + ((size_t)b * SEQ + i0 + m0 + g + 8) * D_MODEL + h * HD;
    #pragma unroll
    for (int nb = 0; nb < 8; nb++) {
        float2 v0 = make_float2(O[nb][0] * inv0, O[nb][1] * inv0);
        float2 v1 = make_float2(O[nb][2] * inv1, O[nb][3] * inv1);
        *(float2*)(o0 + nb * 8 + 2 * q) = v0;
        *(float2*)(o1 + nb * 8 + 2 * q) = v1;
    }
}

extern "C" void kernel_launch(void* const* d_in, const int* in_sizes, int n_in,
                              void* d_out, int out_size) {
    const float* x = (const float*)d_in[0];
    float* out = (float*)d_out;
    const int smem_bytes = (64 * KVS + 64 * 64 + 4 * 16 * PS) * sizeof(float);  // 51200
    cudaFuncSetAttribute(fa_tf32_kernel,
                         cudaFuncAttributeMaxDynamicSharedMemorySize, smem_bytes);
    dim3 grid(SEQ / BM, BATCH * N_HEAD);
    fa_tf32_kernel<<<grid, 128, smem_bytes>>>(x, out);
}